// round 1
// baseline (speedup 1.0000x reference)
#include <cuda_runtime.h>
#include <math.h>

#define Bn 4
#define Tn 2048
#define Dn 1024
#define Hn 16
#define HDn 64
#define En 16
#define Rn 64                     // Bn*En active rows
#define QK_SCALE 0.35355339059327373f   // hd^-0.25
#define SM_SCALE 0.125f                 // 1/sqrt(hd)

// ---------------- scratch (static device globals; no allocation) ----------
__device__ float g_xn[Rn * Dn];
__device__ float g_q[Rn * Dn];
__device__ float g_k[Rn * Dn];
__device__ float g_v[Rn * Dn];
__device__ float g_ai1[Rn * Dn];
__device__ float g_ai2[Rn * Dn];
__device__ float g_diffsum;

// ---------------- helpers -------------------------------------------------
__device__ __forceinline__ float warpReduceSum(float v) {
#pragma unroll
    for (int o = 16; o > 0; o >>= 1) v += __shfl_xor_sync(0xffffffffu, v, o);
    return v;
}

// 256-thread block reduce; result broadcast to all threads
__device__ __forceinline__ float blockReduce256(float v, float* sh) {
    __syncthreads();
    v = warpReduceSum(v);
    int wid = threadIdx.x >> 5;
    if ((threadIdx.x & 31) == 0) sh[wid] = v;
    __syncthreads();
    if (threadIdx.x < 32) {
        float t = (threadIdx.x < 8) ? sh[threadIdx.x] : 0.f;
        t = warpReduceSum(t);
        if (threadIdx.x == 0) sh[0] = t;
    }
    __syncthreads();
    return sh[0];
}

// ======================= K1: LayerNorm(first 16 tokens) + bo fill =========
__global__ __launch_bounds__(256) void k_ln_fill(
    const float* __restrict__ x, const float* __restrict__ lna,
    const float* __restrict__ bo, float* __restrict__ out) {
    if (blockIdx.x < Rn) {
        __shared__ float sh[8];
        if (blockIdx.x == 0 && threadIdx.x == 0) g_diffsum = 0.f;
        int r = blockIdx.x;
        int b = r >> 4, t = r & 15;
        const float* xr = x + ((size_t)(b * Tn + t)) * Dn;
        int tid = threadIdx.x;
        float v[4];
        float s = 0.f;
#pragma unroll
        for (int i = 0; i < 4; i++) { v[i] = xr[tid + i * 256]; s += v[i]; }
        s = blockReduce256(s, sh);
        float mean = s * (1.f / 1024.f);
        float sq = 0.f;
#pragma unroll
        for (int i = 0; i < 4; i++) { float d = v[i] - mean; sq += d * d; }
        sq = blockReduce256(sq, sh);
        float inv = rsqrtf(sq * (1.f / 1024.f) + 1e-5f);
#pragma unroll
        for (int i = 0; i < 4; i++) {
            int j = tid + i * 256;
            g_xn[r * Dn + j] = (v[i] - mean) * inv * lna[j];
        }
    } else {
        // fill the ENTIRE output with bo (rows t<16 are overwritten by K4)
        const float4* bo4 = (const float4*)bo;
        float4* out4 = (float4*)out;
        size_t nb = gridDim.x - Rn;
        size_t total4 = (size_t)Bn * Tn * Dn / 4;  // 2,097,152
        size_t start = (size_t)(blockIdx.x - Rn) * 256 + threadIdx.x;
        size_t stride = nb * 256;                  // multiple of 256 -> (i&255) fixed
        float4 bv4 = bo4[start & 255];
        for (size_t i = start; i < total4; i += stride) out4[i] = bv4;
    }
}

// ======================= K2: q,k,v for the 64 active rows =================
// y = xn(64x1024) @ W^T(1024x1024), 16-col tiles, 2x2 register blocking
__global__ __launch_bounds__(256) void k_qkv(
    const float* __restrict__ Wq, const float* __restrict__ bq,
    const float* __restrict__ Wk, const float* __restrict__ Wv,
    const float* __restrict__ bv) {
    __shared__ float a_sh[64 * 65];
    __shared__ float w_sh[64 * 17];
    int m = blockIdx.x >> 6;              // 0=q 1=k 2=v
    int j0 = (blockIdx.x & 63) << 4;
    const float* W = (m == 0) ? Wq : (m == 1) ? Wk : Wv;
    int tid = threadIdx.x;
    int lane = tid & 31;
    int cg = tid >> 5;                    // 0..7
    float acc00 = 0, acc01 = 0, acc10 = 0, acc11 = 0;
    for (int k0 = 0; k0 < Dn; k0 += 64) {
#pragma unroll
        for (int i = 0; i < 16; i++) {
            int idx = tid + i * 256;      // r*64 + kk
            int r = idx >> 6, kk = idx & 63;
            a_sh[kk * 65 + r] = g_xn[r * Dn + k0 + kk];
        }
#pragma unroll
        for (int i = 0; i < 4; i++) {
            int idx = tid + i * 256;      // c*64 + kk
            int c = idx >> 6, kk = idx & 63;
            w_sh[kk * 17 + c] = W[(size_t)(j0 + c) * Dn + k0 + kk];
        }
        __syncthreads();
#pragma unroll 16
        for (int kk = 0; kk < 64; kk++) {
            float a0 = a_sh[kk * 65 + lane];
            float a1 = a_sh[kk * 65 + lane + 32];
            float w0 = w_sh[kk * 17 + cg];
            float w1 = w_sh[kk * 17 + cg + 8];
            acc00 = fmaf(a0, w0, acc00);
            acc01 = fmaf(a0, w1, acc01);
            acc10 = fmaf(a1, w0, acc10);
            acc11 = fmaf(a1, w1, acc11);
        }
        __syncthreads();
    }
    float* dst = (m == 0) ? g_q : (m == 1) ? g_k : g_v;
    int c0 = j0 + cg, c1 = j0 + cg + 8;
    float o00, o01, o10, o11;
    if (m == 0) {
        o00 = (acc00 + bq[c0]) * QK_SCALE; o01 = (acc01 + bq[c1]) * QK_SCALE;
        o10 = (acc10 + bq[c0]) * QK_SCALE; o11 = (acc11 + bq[c1]) * QK_SCALE;
    } else if (m == 1) {
        o00 = acc00 * QK_SCALE; o01 = acc01 * QK_SCALE;
        o10 = acc10 * QK_SCALE; o11 = acc11 * QK_SCALE;
    } else {
        o00 = acc00 + bv[c0]; o01 = acc01 + bv[c1];
        o10 = acc10 + bv[c0]; o11 = acc11 + bv[c1];
    }
    dst[lane * Dn + c0] = o00;        dst[lane * Dn + c1] = o01;
    dst[(lane + 32) * Dn + c0] = o10; dst[(lane + 32) * Dn + c1] = o11;
}

// ======================= K3: per-(b,h) 3-iteration attention ==============
__device__ __forceinline__ void stage_w(float* w, const float* __restrict__ W, int tid) {
#pragma unroll
    for (int i = 0; i < 16; i++) {
        int idx = tid + i * 256;          // j*64 + d
        w[(idx >> 6) * 65 + (idx & 63)] = W[idx];
    }
}

// outb[16][64] = in[16][64] @ W^T + bl ; W staged as w[j*65+d]
__device__ __forceinline__ void small_gemm(const float* in, const float* w,
                                           const float* __restrict__ bl,
                                           float* outb, int tid) {
    int e = tid >> 4, jb = (tid & 15) * 4, lane = tid & 31;
    float a0 = bl[jb], a1 = bl[jb + 1], a2 = bl[jb + 2], a3 = bl[jb + 3];
#pragma unroll
    for (int dd = 0; dd < 64; dd++) {
        int d = (dd + lane) & 63;         // skewed, conflict-free
        float iv = in[e * 64 + d];
        a0 = fmaf(iv, w[(jb + 0) * 65 + d], a0);
        a1 = fmaf(iv, w[(jb + 1) * 65 + d], a1);
        a2 = fmaf(iv, w[(jb + 2) * 65 + d], a2);
        a3 = fmaf(iv, w[(jb + 3) * 65 + d], a3);
    }
    outb[e * 64 + jb] = a0;     outb[e * 64 + jb + 1] = a1;
    outb[e * 64 + jb + 2] = a2; outb[e * 64 + jb + 3] = a3;
}

// in-place LayerNorm of 16 rows x 64, times weight lw and scalar s
__device__ __forceinline__ void ln_inplace(float* buf, const float* __restrict__ lw,
                                           float s, int tid) {
    int wid = tid >> 5, lane = tid & 31;
    for (int rr = wid; rr < 16; rr += 8) {
        float v0 = buf[rr * 64 + lane], v1 = buf[rr * 64 + lane + 32];
        float sum = warpReduceSum(v0 + v1);
        float mean = sum * (1.f / 64.f);
        float d0 = v0 - mean, d1 = v1 - mean;
        float sq = warpReduceSum(d0 * d0 + d1 * d1);
        float inv = rsqrtf(sq * (1.f / 64.f) + 1e-5f);
        buf[rr * 64 + lane] = d0 * inv * lw[lane] * s;
        buf[rr * 64 + lane + 32] = d1 * inv * lw[lane + 32] * s;
    }
}

__global__ __launch_bounds__(256) void k_iter(
    const float* __restrict__ Wlq, const float* __restrict__ blq,
    const float* __restrict__ Wlk, const float* __restrict__ blk,
    const float* __restrict__ Wlv, const float* __restrict__ blv,
    const float* __restrict__ lnc, const float* __restrict__ lnd,
    const float* __restrict__ temp_p) {
    __shared__ float qcur[1024], kcur[1024], vcur[1024];
    __shared__ float ql[1024], kl[1024], vl[1024];
    __shared__ float aiprev[1024];
    __shared__ float p[256];
    __shared__ float w[64 * 65];
    __shared__ float red[8];

    int tid = threadIdx.x;
    int bb = blockIdx.x >> 4;
    int h = blockIdx.x & 15;
    for (int i = tid; i < 1024; i += 256) {
        int e = i >> 6, d = i & 63;
        size_t g = (size_t)(bb * En + e) * Dn + h * HDn + d;
        qcur[i] = g_q[g];
        kcur[i] = g_k[g];
        vcur[i] = g_v[g];
    }
    float temp0 = temp_p[0];
    __syncthreads();

    for (int it = 0; it < 3; it++) {
        stage_w(w, Wlq, tid); __syncthreads();
        small_gemm(qcur, w, blq, ql, tid); __syncthreads();
        stage_w(w, Wlk, tid); __syncthreads();
        small_gemm(kcur, w, blk, kl, tid); __syncthreads();
        stage_w(w, Wlv, tid); __syncthreads();
        small_gemm(vcur, w, blv, vl, tid); __syncthreads();

        // kcur,vcur <- kl,vl (pre-LN!) for next iteration
        for (int i = tid; i < 1024; i += 256) { kcur[i] = kl[i]; vcur[i] = vl[i]; }
        __syncthreads();

        float t_it = temp0 + 0.005f * (float)it;
        float tsc = ((t_it != 1.0f) && (t_it > 0.f)) ? rsqrtf(t_it) : 1.0f;
        ln_inplace(ql, lnc, tsc * SM_SCALE, tid);   // fold sm_scale into qs
        ln_inplace(kl, lnd, 1.0f, tid);
        __syncthreads();

        {   // logits (16x16)
            int e = tid >> 4, f = tid & 15, lane = tid & 31;
            float acc = 0.f;
#pragma unroll
            for (int dd = 0; dd < 64; dd++) {
                int d = (dd + lane) & 63;
                acc = fmaf(ql[e * 64 + d], kl[f * 64 + d], acc);
            }
            p[tid] = acc;
        }
        __syncthreads();
        if (tid < 16) {                              // softmax per row
            float mx = -1e30f;
#pragma unroll
            for (int f = 0; f < 16; f++) mx = fmaxf(mx, p[tid * 16 + f]);
            float s = 0.f;
#pragma unroll
            for (int f = 0; f < 16; f++) {
                float ex = expf(p[tid * 16 + f] - mx);
                p[tid * 16 + f] = ex; s += ex;
            }
            float inv = 1.f / s;
#pragma unroll
            for (int f = 0; f < 16; f++) p[tid * 16 + f] *= inv;
        }
        __syncthreads();
        {   // ai = softmax @ vl, plus updates
            int e = tid >> 4, jb = (tid & 15) * 4;
            float b0 = 0, b1 = 0, b2 = 0, b3 = 0;
#pragma unroll
            for (int f = 0; f < 16; f++) {
                float pv = p[e * 16 + f];
                const float* vr = &vl[f * 64 + jb];
                b0 = fmaf(pv, vr[0], b0);
                b1 = fmaf(pv, vr[1], b1);
                b2 = fmaf(pv, vr[2], b2);
                b3 = fmaf(pv, vr[3], b3);
            }
            int base = e * 64 + jb;
            float ds = 0.f;
            if (it == 1) {
                ds = fabsf(b0 - aiprev[base]) + fabsf(b1 - aiprev[base + 1]) +
                     fabsf(b2 - aiprev[base + 2]) + fabsf(b3 - aiprev[base + 3]);
            }
            if (it == 0) {
                aiprev[base] = b0; aiprev[base + 1] = b1;
                aiprev[base + 2] = b2; aiprev[base + 3] = b3;
            }
            if (it >= 1) {
                float* dst = (it == 1) ? g_ai1 : g_ai2;
                size_t g = (size_t)(bb * En + e) * Dn + h * HDn + jb;
                dst[g] = b0; dst[g + 1] = b1; dst[g + 2] = b2; dst[g + 3] = b3;
            }
            qcur[base] += b0; qcur[base + 1] += b1;
            qcur[base + 2] += b2; qcur[base + 3] += b3;
            if (it == 1) {
                float tot = blockReduce256(ds, red);
                if (tid == 0) atomicAdd(&g_diffsum, tot);
            }
        }
        __syncthreads();
    }
}

// ======================= K4: select ai, project with Wo, write rows t<16 ==
__global__ __launch_bounds__(256) void k_out(
    const float* __restrict__ Wo, const float* __restrict__ bo,
    const float* __restrict__ thrp, const float* __restrict__ facp,
    float* __restrict__ out) {
    __shared__ float a_sh[64 * 65];
    __shared__ float w_sh[64 * 17];
    float diff1 = g_diffsum * (1.0f / 8388608.0f);  // mean over B*H*T*hd
    const float* A = (diff1 < thrp[0] + facp[0] * diff1) ? g_ai1 : g_ai2;
    int j0 = blockIdx.x << 4;
    int tid = threadIdx.x, lane = tid & 31, cg = tid >> 5;
    float acc00 = 0, acc01 = 0, acc10 = 0, acc11 = 0;
    for (int k0 = 0; k0 < Dn; k0 += 64) {
#pragma unroll
        for (int i = 0; i < 16; i++) {
            int idx = tid + i * 256;
            int r = idx >> 6, kk = idx & 63;
            a_sh[kk * 65 + r] = A[r * Dn + k0 + kk];
        }
#pragma unroll
        for (int i = 0; i < 4; i++) {
            int idx = tid + i * 256;
            int c = idx >> 6, kk = idx & 63;
            w_sh[kk * 17 + c] = Wo[(size_t)(j0 + c) * Dn + k0 + kk];
        }
        __syncthreads();
#pragma unroll 16
        for (int kk = 0; kk < 64; kk++) {
            float a0 = a_sh[kk * 65 + lane];
            float a1 = a_sh[kk * 65 + lane + 32];
            float w0 = w_sh[kk * 17 + cg];
            float w1 = w_sh[kk * 17 + cg + 8];
            acc00 = fmaf(a0, w0, acc00);
            acc01 = fmaf(a0, w1, acc01);
            acc10 = fmaf(a1, w0, acc10);
            acc11 = fmaf(a1, w1, acc11);
        }
        __syncthreads();
    }
    int c0 = j0 + cg, c1 = j0 + cg + 8;
    int b0r = lane >> 4, t0r = lane & 15;
    int b1r = (lane + 32) >> 4, t1r = (lane + 32) & 15;
    out[((size_t)(b0r * Tn + t0r)) * Dn + c0] = acc00 + bo[c0];
    out[((size_t)(b0r * Tn + t0r)) * Dn + c1] = acc01 + bo[c1];
    out[((size_t)(b1r * Tn + t1r)) * Dn + c0] = acc10 + bo[c0];
    out[((size_t)(b1r * Tn + t1r)) * Dn + c1] = acc11 + bo[c1];
}

// ======================= launch ===========================================
extern "C" void kernel_launch(void* const* d_in, const int* in_sizes, int n_in,
                              void* d_out, int out_size) {
    (void)in_sizes; (void)n_in; (void)out_size;
    const float* x    = (const float*)d_in[0];
    const float* Wq   = (const float*)d_in[1];
    const float* bq   = (const float*)d_in[2];
    const float* Wk   = (const float*)d_in[3];
    const float* Wv   = (const float*)d_in[4];
    const float* bv   = (const float*)d_in[5];
    const float* Wo   = (const float*)d_in[6];
    const float* bo   = (const float*)d_in[7];
    const float* lna  = (const float*)d_in[8];
    const float* lnc  = (const float*)d_in[9];
    const float* lnd  = (const float*)d_in[10];
    const float* Wlq  = (const float*)d_in[11];
    const float* blq  = (const float*)d_in[12];
    const float* Wlk  = (const float*)d_in[13];
    const float* blk  = (const float*)d_in[14];
    const float* Wlv  = (const float*)d_in[15];
    const float* blv  = (const float*)d_in[16];
    const float* temp = (const float*)d_in[17];
    const float* thr  = (const float*)d_in[18];
    const float* fac  = (const float*)d_in[19];
    float* out = (float*)d_out;

    k_ln_fill<<<512, 256>>>(x, lna, bo, out);                 // LN + bo fill + zero diff
    k_qkv<<<192, 256>>>(Wq, bq, Wk, Wv, bv);                  // q,k,v (64 rows)
    k_iter<<<64, 256>>>(Wlq, blq, Wlk, blk, Wlv, blv, lnc, lnd, temp);
    k_out<<<64, 256>>>(Wo, bo, thr, fac, out);                // select + Wo + write
}

// round 3
// speedup vs baseline: 1.3966x; 1.3966x over previous
#include <cuda_runtime.h>
#include <math.h>

#define Bn 4
#define Tn 2048
#define Dn 1024
#define Hn 16
#define HDn 64
#define En 16
#define Rn 64                     // Bn*En active rows
#define QK_SCALE 0.35355339059327373f   // hd^-0.25
#define SM_SCALE 0.125f                 // 1/sqrt(hd)

typedef unsigned long long u64;

// ---------------- scratch (static device globals; no allocation) ----------
__device__ float g_xn[Rn * Dn];
__device__ float g_q[Rn * Dn];
__device__ float g_k[Rn * Dn];
__device__ float g_v[Rn * Dn];
__device__ float g_ai1[Rn * Dn];
__device__ float g_ai2[Rn * Dn];
__device__ float g_diffsum;

// ---------------- helpers -------------------------------------------------
__device__ __forceinline__ float warpReduceSum(float v) {
#pragma unroll
    for (int o = 16; o > 0; o >>= 1) v += __shfl_xor_sync(0xffffffffu, v, o);
    return v;
}

__device__ __forceinline__ float blockReduce256(float v, float* sh) {
    __syncthreads();
    v = warpReduceSum(v);
    int wid = threadIdx.x >> 5;
    if ((threadIdx.x & 31) == 0) sh[wid] = v;
    __syncthreads();
    if (threadIdx.x < 32) {
        float t = (threadIdx.x < 8) ? sh[threadIdx.x] : 0.f;
        t = warpReduceSum(t);
        if (threadIdx.x == 0) sh[0] = t;
    }
    __syncthreads();
    return sh[0];
}

// packed fp32x2 FMA (sm_100+): d = a*b + d, lane-wise on a 64-bit pair
__device__ __forceinline__ void ffma2(u64& d, u64 a, u64 b) {
    asm("fma.rn.f32x2 %0, %1, %2, %0;" : "+l"(d) : "l"(a), "l"(b));
}

// ======================= K1: LN(64 rows) + accumulator inits + bo fill ====
__global__ __launch_bounds__(256) void k_ln_fill(
    const float* __restrict__ x, const float* __restrict__ lna,
    const float* __restrict__ bq, const float* __restrict__ bv,
    const float* __restrict__ bo, float* __restrict__ out) {
    if (blockIdx.x < Rn) {
        __shared__ float sh[8];
        if (blockIdx.x == 0 && threadIdx.x == 0) g_diffsum = 0.f;
        int r = blockIdx.x;
        int b = r >> 4, t = r & 15;
        const float* xr = x + ((size_t)(b * Tn + t)) * Dn;
        int tid = threadIdx.x;
        float v[4];
        float s = 0.f;
#pragma unroll
        for (int i = 0; i < 4; i++) { v[i] = xr[tid + i * 256]; s += v[i]; }
        s = blockReduce256(s, sh);
        float mean = s * (1.f / 1024.f);
        float sq = 0.f;
#pragma unroll
        for (int i = 0; i < 4; i++) { float d = v[i] - mean; sq += d * d; }
        sq = blockReduce256(sq, sh);
        float inv = rsqrtf(sq * (1.f / 1024.f) + 1e-5f);
#pragma unroll
        for (int i = 0; i < 4; i++) {
            int j = tid + i * 256;
            g_xn[r * Dn + j] = (v[i] - mean) * inv * lna[j];
        }
    } else if (blockIdx.x < 2 * Rn) {
        // init accumulators with biases (k-split GEMMs atomicAdd onto these)
        int r = blockIdx.x - Rn;
        int tid = threadIdx.x;
#pragma unroll
        for (int i = 0; i < 4; i++) {
            int j = tid + i * 256;
            g_q[r * Dn + j] = bq[j] * QK_SCALE;
            g_k[r * Dn + j] = 0.f;
            g_v[r * Dn + j] = bv[j];
        }
    } else {
        // fill the ENTIRE output with bo (rows t<16 get +Wo-proj via atomics)
        const float4* bo4 = (const float4*)bo;
        float4* out4 = (float4*)out;
        size_t nb = gridDim.x - 2 * Rn;
        size_t total4 = (size_t)Bn * Tn * Dn / 4;  // 2,097,152
        size_t start = (size_t)(blockIdx.x - 2 * Rn) * 256 + threadIdx.x;
        size_t stride = nb * 256;
        float4 bv4 = bo4[start & 255];
        for (size_t i = start; i < total4; i += stride) out4[i] = bv4;
    }
}

// ======================= shared 64x64-tile FFMA2 GEMM core ================
// C[64 x 1024] (+)= A[64x1024] @ W^T ; block = 64-col tile x K-chunk.
// Thread tile 4 rows x 4 cols; accumulators packed along K (even/odd).
__device__ __forceinline__ void gemm64_core(
    const float* __restrict__ A, const float* __restrict__ W,
    int j0, int kbase, int kchunk, u64 acc[4][4],
    float* a_sh, float* w_sh) {
    int tid = threadIdx.x;
    int r0 = (tid & 15) * 4;
    int c0 = (tid >> 4) * 4;
    for (int kt = 0; kt < kchunk; kt += 64) {
        int kb = kbase + kt;
#pragma unroll
        for (int i = tid; i < 1024; i += 256) {
            int row = i >> 4, kq = (i & 15) * 4;
            *(float4*)&a_sh[row * 68 + kq] =
                *(const float4*)&A[(size_t)row * Dn + kb + kq];
            *(float4*)&w_sh[row * 68 + kq] =
                *(const float4*)&W[(size_t)(j0 + row) * Dn + kb + kq];
        }
        __syncthreads();
#pragma unroll 8
        for (int kk = 0; kk < 64; kk += 2) {
            u64 av[4], wv[4];
#pragma unroll
            for (int i = 0; i < 4; i++)
                av[i] = *(const u64*)&a_sh[(r0 + i) * 68 + kk];
#pragma unroll
            for (int j = 0; j < 4; j++)
                wv[j] = *(const u64*)&w_sh[(c0 + j) * 68 + kk];
#pragma unroll
            for (int i = 0; i < 4; i++)
#pragma unroll
                for (int j = 0; j < 4; j++) ffma2(acc[i][j], av[i], wv[j]);
        }
        __syncthreads();
    }
}

// ======================= K2: q,k,v GEMMs (k-split, atomic) ================
// grid (16 coltiles, KSPLIT_QKV, 3 mats)
#define KSPLIT_QKV 8
__global__ __launch_bounds__(256, 3) void k_qkv(
    const float* __restrict__ Wq, const float* __restrict__ Wk,
    const float* __restrict__ Wv) {
    __shared__ __align__(16) float a_sh[64 * 68];
    __shared__ __align__(16) float w_sh[64 * 68];
    int m = blockIdx.z;
    const float* W = (m == 0) ? Wq : (m == 1) ? Wk : Wv;
    float* dst = (m == 0) ? g_q : (m == 1) ? g_k : g_v;
    float scale = (m == 2) ? 1.0f : QK_SCALE;
    int j0 = blockIdx.x * 64;
    int kbase = blockIdx.y * (Dn / KSPLIT_QKV);
    u64 acc[4][4] = {};
    gemm64_core(g_xn, W, j0, kbase, Dn / KSPLIT_QKV, acc, a_sh, w_sh);
    int tid = threadIdx.x;
    int r0 = (tid & 15) * 4, c0 = (tid >> 4) * 4;
#pragma unroll
    for (int i = 0; i < 4; i++)
#pragma unroll
        for (int j = 0; j < 4; j++) {
            float2 f = *(float2*)&acc[i][j];
            atomicAdd(&dst[(size_t)(r0 + i) * Dn + j0 + c0 + j],
                      (f.x + f.y) * scale);
        }
}

// ======================= K3: per-(b,h) 3-iteration attention ==============
__device__ __forceinline__ void stage_w(float* w, const float* __restrict__ W, int tid) {
#pragma unroll
    for (int i = 0; i < 16; i++) {
        int idx = tid + i * 256;          // j*64 + d
        w[(idx >> 6) * 65 + (idx & 63)] = W[idx];
    }
}

__device__ __forceinline__ void small_gemm(const float* in, const float* w,
                                           const float* __restrict__ bl,
                                           float* outb, int tid) {
    int e = tid >> 4, jb = (tid & 15) * 4, lane = tid & 31;
    float a0 = bl[jb], a1 = bl[jb + 1], a2 = bl[jb + 2], a3 = bl[jb + 3];
#pragma unroll
    for (int dd = 0; dd < 64; dd++) {
        int d = (dd + lane) & 63;
        float iv = in[e * 64 + d];
        a0 = fmaf(iv, w[(jb + 0) * 65 + d], a0);
        a1 = fmaf(iv, w[(jb + 1) * 65 + d], a1);
        a2 = fmaf(iv, w[(jb + 2) * 65 + d], a2);
        a3 = fmaf(iv, w[(jb + 3) * 65 + d], a3);
    }
    outb[e * 64 + jb] = a0;     outb[e * 64 + jb + 1] = a1;
    outb[e * 64 + jb + 2] = a2; outb[e * 64 + jb + 3] = a3;
}

__device__ __forceinline__ void ln_inplace(float* buf, const float* __restrict__ lw,
                                           float s, int tid) {
    int wid = tid >> 5, lane = tid & 31;
    for (int rr = wid; rr < 16; rr += 8) {
        float v0 = buf[rr * 64 + lane], v1 = buf[rr * 64 + lane + 32];
        float sum = warpReduceSum(v0 + v1);
        float mean = sum * (1.f / 64.f);
        float d0 = v0 - mean, d1 = v1 - mean;
        float sq = warpReduceSum(d0 * d0 + d1 * d1);
        float inv = rsqrtf(sq * (1.f / 64.f) + 1e-5f);
        buf[rr * 64 + lane] = d0 * inv * lw[lane] * s;
        buf[rr * 64 + lane + 32] = d1 * inv * lw[lane + 32] * s;
    }
}

__global__ __launch_bounds__(256) void k_iter(
    const float* __restrict__ Wlq, const float* __restrict__ blq,
    const float* __restrict__ Wlk, const float* __restrict__ blk,
    const float* __restrict__ Wlv, const float* __restrict__ blv,
    const float* __restrict__ lnc, const float* __restrict__ lnd,
    const float* __restrict__ temp_p) {
    __shared__ float qcur[1024], kcur[1024], vcur[1024];
    __shared__ float ql[1024], kl[1024], vl[1024];
    __shared__ float aiprev[1024];
    __shared__ float p[256];
    __shared__ float w[64 * 65];
    __shared__ float red[8];

    int tid = threadIdx.x;
    int bb = blockIdx.x >> 4;
    int h = blockIdx.x & 15;
    for (int i = tid; i < 1024; i += 256) {
        int e = i >> 6, d = i & 63;
        size_t g = (size_t)(bb * En + e) * Dn + h * HDn + d;
        qcur[i] = g_q[g];
        kcur[i] = g_k[g];
        vcur[i] = g_v[g];
    }
    float temp0 = temp_p[0];
    __syncthreads();

    for (int it = 0; it < 3; it++) {
        stage_w(w, Wlq, tid); __syncthreads();
        small_gemm(qcur, w, blq, ql, tid); __syncthreads();
        stage_w(w, Wlk, tid); __syncthreads();
        small_gemm(kcur, w, blk, kl, tid); __syncthreads();
        stage_w(w, Wlv, tid); __syncthreads();
        small_gemm(vcur, w, blv, vl, tid); __syncthreads();

        for (int i = tid; i < 1024; i += 256) { kcur[i] = kl[i]; vcur[i] = vl[i]; }
        __syncthreads();

        float t_it = temp0 + 0.005f * (float)it;
        float tsc = ((t_it != 1.0f) && (t_it > 0.f)) ? rsqrtf(t_it) : 1.0f;
        ln_inplace(ql, lnc, tsc * SM_SCALE, tid);
        ln_inplace(kl, lnd, 1.0f, tid);
        __syncthreads();

        {   // logits (16x16)
            int e = tid >> 4, f = tid & 15, lane = tid & 31;
            float acc = 0.f;
#pragma unroll
            for (int dd = 0; dd < 64; dd++) {
                int d = (dd + lane) & 63;
                acc = fmaf(ql[e * 64 + d], kl[f * 64 + d], acc);
            }
            p[tid] = acc;
        }
        __syncthreads();
        if (tid < 16) {
            float mx = -1e30f;
#pragma unroll
            for (int f = 0; f < 16; f++) mx = fmaxf(mx, p[tid * 16 + f]);
            float s = 0.f;
#pragma unroll
            for (int f = 0; f < 16; f++) {
                float ex = expf(p[tid * 16 + f] - mx);
                p[tid * 16 + f] = ex; s += ex;
            }
            float inv = 1.f / s;
#pragma unroll
            for (int f = 0; f < 16; f++) p[tid * 16 + f] *= inv;
        }
        __syncthreads();
        {
            int e = tid >> 4, jb = (tid & 15) * 4;
            float b0 = 0, b1 = 0, b2 = 0, b3 = 0;
#pragma unroll
            for (int f = 0; f < 16; f++) {
                float pv = p[e * 16 + f];
                const float* vr = &vl[f * 64 + jb];
                b0 = fmaf(pv, vr[0], b0);
                b1 = fmaf(pv, vr[1], b1);
                b2 = fmaf(pv, vr[2], b2);
                b3 = fmaf(pv, vr[3], b3);
            }
            int base = e * 64 + jb;
            float ds = 0.f;
            if (it == 1) {
                ds = fabsf(b0 - aiprev[base]) + fabsf(b1 - aiprev[base + 1]) +
                     fabsf(b2 - aiprev[base + 2]) + fabsf(b3 - aiprev[base + 3]);
            }
            if (it == 0) {
                aiprev[base] = b0; aiprev[base + 1] = b1;
                aiprev[base + 2] = b2; aiprev[base + 3] = b3;
            }
            if (it >= 1) {
                float* dst = (it == 1) ? g_ai1 : g_ai2;
                size_t g = (size_t)(bb * En + e) * Dn + h * HDn + jb;
                dst[g] = b0; dst[g + 1] = b1; dst[g + 2] = b2; dst[g + 3] = b3;
            }
            qcur[base] += b0; qcur[base + 1] += b1;
            qcur[base + 2] += b2; qcur[base + 3] += b3;
            if (it == 1) {
                float tot = blockReduce256(ds, red);
                if (tid == 0) atomicAdd(&g_diffsum, tot);
            }
        }
        __syncthreads();
    }
}

// ======================= K4: select ai, Wo proj, atomic into out ==========
// grid (16 coltiles, KSPLIT_OUT)
#define KSPLIT_OUT 16
__global__ __launch_bounds__(256, 3) void k_out(
    const float* __restrict__ Wo, const float* __restrict__ thrp,
    const float* __restrict__ facp, float* __restrict__ out) {
    __shared__ __align__(16) float a_sh[64 * 68];
    __shared__ __align__(16) float w_sh[64 * 68];
    float diff1 = g_diffsum * (1.0f / 8388608.0f);  // mean over B*H*T*hd
    const float* A = (diff1 < thrp[0] + facp[0] * diff1) ? g_ai1 : g_ai2;
    int j0 = blockIdx.x * 64;
    int kbase = blockIdx.y * (Dn / KSPLIT_OUT);
    u64 acc[4][4] = {};
    gemm64_core(A, Wo, j0, kbase, Dn / KSPLIT_OUT, acc, a_sh, w_sh);
    int tid = threadIdx.x;
    int r0 = (tid & 15) * 4, c0 = (tid >> 4) * 4;
#pragma unroll
    for (int i = 0; i < 4; i++) {
        int r = r0 + i;
        int b = r >> 4, t = r & 15;
        size_t base = ((size_t)(b * Tn + t)) * Dn + j0 + c0;
#pragma unroll
        for (int j = 0; j < 4; j++) {
            float2 f = *(float2*)&acc[i][j];
            atomicAdd(&out[base + j], f.x + f.y);
        }
    }
}

// ======================= launch ===========================================
extern "C" void kernel_launch(void* const* d_in, const int* in_sizes, int n_in,
                              void* d_out, int out_size) {
    (void)in_sizes; (void)n_in; (void)out_size;
    const float* x    = (const float*)d_in[0];
    const float* Wq   = (const float*)d_in[1];
    const float* bq   = (const float*)d_in[2];
    const float* Wk   = (const float*)d_in[3];
    const float* Wv   = (const float*)d_in[4];
    const float* bv   = (const float*)d_in[5];
    const float* Wo   = (const float*)d_in[6];
    const float* bo   = (const float*)d_in[7];
    const float* lna  = (const float*)d_in[8];
    const float* lnc  = (const float*)d_in[9];
    const float* lnd  = (const float*)d_in[10];
    const float* Wlq  = (const float*)d_in[11];
    const float* blq  = (const float*)d_in[12];
    const float* Wlk  = (const float*)d_in[13];
    const float* blk  = (const float*)d_in[14];
    const float* Wlv  = (const float*)d_in[15];
    const float* blv  = (const float*)d_in[16];
    const float* temp = (const float*)d_in[17];
    const float* thr  = (const float*)d_in[18];
    const float* fac  = (const float*)d_in[19];
    float* out = (float*)d_out;

    k_ln_fill<<<1024, 256>>>(x, lna, bq, bv, bo, out);
    k_qkv<<<dim3(16, KSPLIT_QKV, 3), 256>>>(Wq, Wk, Wv);
    k_iter<<<64, 256>>>(Wlq, blq, Wlk, blk, Wlv, blv, lnc, lnd, temp);
    k_out<<<dim3(16, KSPLIT_OUT, 1), 256>>>(Wo, thr, fac, out);
}

// round 4
// speedup vs baseline: 1.9508x; 1.3968x over previous
#include <cuda_runtime.h>
#include <math.h>

#define Bn 4
#define Tn 2048
#define Dn 1024
#define Hn 16
#define HDn 64
#define En 16
#define Rn 64                     // Bn*En active rows
#define QK_SCALE 0.35355339059327373f   // hd^-0.25
#define SM_SCALE 0.125f                 // 1/sqrt(hd)

typedef unsigned long long u64;

// ---------------- scratch (static device globals; no allocation) ----------
__device__ float g_xn[Rn * Dn];
__device__ float g_q[Rn * Dn];
__device__ float g_k[Rn * Dn];
__device__ float g_v[Rn * Dn];
__device__ float g_ai1[Rn * Dn];
__device__ float g_ai2[Rn * Dn];
__device__ float g_diffsum;

// ---------------- helpers -------------------------------------------------
__device__ __forceinline__ float warpReduceSum(float v) {
#pragma unroll
    for (int o = 16; o > 0; o >>= 1) v += __shfl_xor_sync(0xffffffffu, v, o);
    return v;
}

__device__ __forceinline__ float blockReduce256(float v, float* sh) {
    __syncthreads();
    v = warpReduceSum(v);
    int wid = threadIdx.x >> 5;
    if ((threadIdx.x & 31) == 0) sh[wid] = v;
    __syncthreads();
    if (threadIdx.x < 32) {
        float t = (threadIdx.x < 8) ? sh[threadIdx.x] : 0.f;
        t = warpReduceSum(t);
        if (threadIdx.x == 0) sh[0] = t;
    }
    __syncthreads();
    return sh[0];
}

// packed fp32x2 FMA (sm_100+): d = a*b + d, lane-wise on a 64-bit pair
__device__ __forceinline__ void ffma2(u64& d, u64 a, u64 b) {
    asm("fma.rn.f32x2 %0, %1, %2, %0;" : "+l"(d) : "l"(a), "l"(b));
}

// ======================= K1: LN(64 rows) + accumulator inits + bo fill ====
__global__ __launch_bounds__(256) void k_ln_fill(
    const float* __restrict__ x, const float* __restrict__ lna,
    const float* __restrict__ bq, const float* __restrict__ bv,
    const float* __restrict__ bo, float* __restrict__ out) {
    if (blockIdx.x < Rn) {
        __shared__ float sh[8];
        if (blockIdx.x == 0 && threadIdx.x == 0) g_diffsum = 0.f;
        int r = blockIdx.x;
        int b = r >> 4, t = r & 15;
        const float* xr = x + ((size_t)(b * Tn + t)) * Dn;
        int tid = threadIdx.x;
        float v[4];
        float s = 0.f;
#pragma unroll
        for (int i = 0; i < 4; i++) { v[i] = xr[tid + i * 256]; s += v[i]; }
        s = blockReduce256(s, sh);
        float mean = s * (1.f / 1024.f);
        float sq = 0.f;
#pragma unroll
        for (int i = 0; i < 4; i++) { float d = v[i] - mean; sq += d * d; }
        sq = blockReduce256(sq, sh);
        float inv = rsqrtf(sq * (1.f / 1024.f) + 1e-5f);
#pragma unroll
        for (int i = 0; i < 4; i++) {
            int j = tid + i * 256;
            g_xn[r * Dn + j] = (v[i] - mean) * inv * lna[j];
        }
    } else if (blockIdx.x < 2 * Rn) {
        // init accumulators with biases (k-split GEMMs atomicAdd onto these)
        int r = blockIdx.x - Rn;
        int tid = threadIdx.x;
#pragma unroll
        for (int i = 0; i < 4; i++) {
            int j = tid + i * 256;
            g_q[r * Dn + j] = bq[j] * QK_SCALE;
            g_k[r * Dn + j] = 0.f;
            g_v[r * Dn + j] = bv[j];
        }
    } else {
        // fill the ENTIRE output with bo (rows t<16 get +Wo-proj via atomics)
        const float4* bo4 = (const float4*)bo;
        float4* out4 = (float4*)out;
        size_t nb = gridDim.x - 2 * Rn;
        size_t total4 = (size_t)Bn * Tn * Dn / 4;  // 2,097,152
        size_t start = (size_t)(blockIdx.x - 2 * Rn) * 256 + threadIdx.x;
        size_t stride = nb * 256;
        float4 bv4 = bo4[start & 255];
        for (size_t i = start; i < total4; i += stride) out4[i] = bv4;
    }
}

// ======================= double-buffered 64x64-tile FFMA2 GEMM core =======
// acc (+)= A[64 x 64*NT] @ W^T tile; rows interleaved (rl + 16*i) to keep
// LDS conflicts at 2-way; register prefetch of next tile overlaps compute.
#define TS 68                      // smem row stride (floats)
template <int NT>
__device__ __forceinline__ void gemm_db(
    const float* __restrict__ A, const float* __restrict__ W,
    int j0, int kbase, u64 acc[4][4], float* sh) {
    int tid = threadIdx.x;
    int rl = tid & 15;             // rows rl, rl+16, rl+32, rl+48
    int c0 = (tid >> 4) * 4;
    float4 pa[4], pw[4];
#pragma unroll
    for (int i = 0; i < 4; i++) {
        int idx = tid + i * 256;
        int row = idx >> 4, kq = (idx & 15) * 4;
        pa[i] = *(const float4*)&A[(size_t)row * Dn + kbase + kq];
        pw[i] = *(const float4*)&W[(size_t)(j0 + row) * Dn + kbase + kq];
    }
    for (int t = 0; t < NT; t++) {
        float* as = sh + (t & 1) * (2 * 64 * TS);
        float* ws = as + 64 * TS;
#pragma unroll
        for (int i = 0; i < 4; i++) {
            int idx = tid + i * 256;
            int row = idx >> 4, kq = (idx & 15) * 4;
            *(float4*)&as[row * TS + kq] = pa[i];
            *(float4*)&ws[row * TS + kq] = pw[i];
        }
        __syncthreads();
        if (t + 1 < NT) {
            int kb = kbase + (t + 1) * 64;
#pragma unroll
            for (int i = 0; i < 4; i++) {
                int idx = tid + i * 256;
                int row = idx >> 4, kq = (idx & 15) * 4;
                pa[i] = *(const float4*)&A[(size_t)row * Dn + kb + kq];
                pw[i] = *(const float4*)&W[(size_t)(j0 + row) * Dn + kb + kq];
            }
        }
#pragma unroll 4
        for (int kk = 0; kk < 64; kk += 2) {
            u64 av[4], wv[4];
#pragma unroll
            for (int i = 0; i < 4; i++)
                av[i] = *(const u64*)&as[(rl + 16 * i) * TS + kk];
#pragma unroll
            for (int j = 0; j < 4; j++)
                wv[j] = *(const u64*)&ws[(c0 + j) * TS + kk];
#pragma unroll
            for (int i = 0; i < 4; i++)
#pragma unroll
                for (int j = 0; j < 4; j++) ffma2(acc[i][j], av[i], wv[j]);
        }
    }
}
#define GEMM_SMEM (4 * 64 * TS * 4)   // 69632 bytes

// ======================= K2: q,k,v GEMMs (k-split, atomic) ================
#define KSPLIT_QKV 4
__global__ __launch_bounds__(256, 2) void k_qkv(
    const float* __restrict__ Wq, const float* __restrict__ Wk,
    const float* __restrict__ Wv) {
    extern __shared__ float sh[];
    int m = blockIdx.z;
    const float* W = (m == 0) ? Wq : (m == 1) ? Wk : Wv;
    float* dst = (m == 0) ? g_q : (m == 1) ? g_k : g_v;
    float scale = (m == 2) ? 1.0f : QK_SCALE;
    int j0 = blockIdx.x * 64;
    int kbase = blockIdx.y * (Dn / KSPLIT_QKV);
    u64 acc[4][4] = {};
    gemm_db<Dn / KSPLIT_QKV / 64>(g_xn, W, j0, kbase, acc, sh);
    int tid = threadIdx.x;
    int rl = tid & 15, c0 = (tid >> 4) * 4;
#pragma unroll
    for (int i = 0; i < 4; i++) {
        int row = rl + 16 * i;
#pragma unroll
        for (int j = 0; j < 4; j++) {
            float2 f = *(float2*)&acc[i][j];
            atomicAdd(&dst[(size_t)row * Dn + j0 + c0 + j], (f.x + f.y) * scale);
        }
    }
}

// ======================= K3: per-(b,h) 3-iteration attention ==============
#define WST 66                     // small-gemm weight smem row stride
__global__ __launch_bounds__(256) void k_iter(
    const float* __restrict__ Wlq, const float* __restrict__ blq,
    const float* __restrict__ Wlk, const float* __restrict__ blk,
    const float* __restrict__ Wlv, const float* __restrict__ blv,
    const float* __restrict__ lnc, const float* __restrict__ lnd,
    const float* __restrict__ temp_p) {
    extern __shared__ float sm[];
    float* w_all  = sm;                     // 3 * 64*WST = 12672
    float* qcur   = w_all + 3 * 64 * WST;   // 1024 each
    float* kcur   = qcur + 1024;
    float* vcur   = kcur + 1024;
    float* qlb    = vcur + 1024;
    float* klb    = qlb + 1024;
    float* aiprev = klb + 1024;
    float* p      = aiprev + 1024;          // 256
    float* red    = p + 256;                // 32

    int tid = threadIdx.x;
    int lane = tid & 31;
    int bb = blockIdx.x >> 4;
    int h = blockIdx.x & 15;

    // stage all three Wl matrices once
    for (int idx = tid; idx < 3 * 4096; idx += 256) {
        int m = idx >> 12, r = idx & 4095, j = r >> 6, d = r & 63;
        const float* Wm = (m == 0) ? Wlq : (m == 1) ? Wlk : Wlv;
        w_all[m * 64 * WST + j * WST + d] = Wm[r];
    }
    for (int i = tid; i < 1024; i += 256) {
        int e = i >> 6, d = i & 63;
        size_t g = (size_t)(bb * En + e) * Dn + h * HDn + d;
        qcur[i] = g_q[g];
        kcur[i] = g_k[g];
        vcur[i] = g_v[g];
    }
    float temp0 = temp_p[0];
    __syncthreads();

    // per-thread gemm mapping (threads 0..191)
    int m = tid / 64;
    int u = tid & 63;
    int e_l = u & 3;                // rows e_l + 4*i
    int j0 = (u >> 2) * 4;          // cols j0..j0+3

    for (int it = 0; it < 3; it++) {
        // ---- fused ql/kl/vl small-GEMMs (FFMA2, 4x4 tiles) ----
        u64 acc[4][4] = {};
        if (tid < 192) {
            const float* in = (m == 0) ? qcur : (m == 1) ? kcur : vcur;
            const float* wm = w_all + m * 64 * WST;
#pragma unroll 4
            for (int dd = 0; dd < 32; dd++) {
                int d = (2 * (dd + lane)) & 62;    // lane skew: ~2-way max
                u64 iv[4], wv[4];
#pragma unroll
                for (int i = 0; i < 4; i++)
                    iv[i] = *(const u64*)&in[(e_l + 4 * i) * 64 + d];
#pragma unroll
                for (int j = 0; j < 4; j++)
                    wv[j] = *(const u64*)&wm[(j0 + j) * WST + d];
#pragma unroll
                for (int i = 0; i < 4; i++)
#pragma unroll
                    for (int j = 0; j < 4; j++) ffma2(acc[i][j], iv[i], wv[j]);
            }
        }
        __syncthreads();   // all reads of qcur/kcur/vcur complete
        if (tid < 192) {
            const float* bl = (m == 0) ? blq : (m == 1) ? blk : blv;
#pragma unroll
            for (int i = 0; i < 4; i++) {
                int e = e_l + 4 * i;
#pragma unroll
                for (int j = 0; j < 4; j++) {
                    float2 f = *(float2*)&acc[i][j];
                    float val = f.x + f.y + bl[j0 + j];
                    int o = e * 64 + j0 + j;
                    if (m == 0) qlb[o] = val;
                    else if (m == 1) { klb[o] = val; kcur[o] = val; }
                    else vcur[o] = val;       // vl (pre-LN, used by AV too)
                }
            }
        }
        __syncthreads();

        // ---- LN(qlb)*tsc*SM_SCALE, LN(klb) : 32 rows over 8 warps ----
        float t_it = temp0 + 0.005f * (float)it;
        float tsc = ((t_it != 1.0f) && (t_it > 0.f)) ? rsqrtf(t_it) : 1.0f;
        int wid = tid >> 5;
        for (int rr = wid; rr < 32; rr += 8) {
            float* buf = (rr < 16) ? (qlb + rr * 64) : (klb + (rr - 16) * 64);
            const float* lw = (rr < 16) ? lnc : lnd;
            float s = (rr < 16) ? tsc * SM_SCALE : 1.0f;
            float v0 = buf[lane], v1 = buf[lane + 32];
            float sum = warpReduceSum(v0 + v1);
            float mean = sum * (1.f / 64.f);
            float d0 = v0 - mean, d1 = v1 - mean;
            float sq = warpReduceSum(d0 * d0 + d1 * d1);
            float inv = rsqrtf(sq * (1.f / 64.f) + 1e-5f);
            buf[lane] = d0 * inv * lw[lane] * s;
            buf[lane + 32] = d1 * inv * lw[lane + 32] * s;
        }
        __syncthreads();

        // ---- logits (16x16) with FFMA2 + lane skew ----
        {
            int e = tid >> 4, f = tid & 15;
            u64 a2 = 0;
#pragma unroll 4
            for (int dd = 0; dd < 32; dd++) {
                int d = (2 * (dd + lane)) & 62;
                ffma2(a2, *(const u64*)&qlb[e * 64 + d],
                          *(const u64*)&klb[f * 64 + d]);
            }
            float2 f2 = *(float2*)&a2;
            p[tid] = f2.x + f2.y;
        }
        __syncthreads();
        if (tid < 16) {                        // softmax per row
            float mx = -1e30f;
#pragma unroll
            for (int f = 0; f < 16; f++) mx = fmaxf(mx, p[tid * 16 + f]);
            float s = 0.f;
#pragma unroll
            for (int f = 0; f < 16; f++) {
                float ex = expf(p[tid * 16 + f] - mx);
                p[tid * 16 + f] = ex; s += ex;
            }
            float inv = 1.f / s;
#pragma unroll
            for (int f = 0; f < 16; f++) p[tid * 16 + f] *= inv;
        }
        __syncthreads();

        // ---- ai = softmax @ vl ; diff; store; qcur update ----
        {
            int e = tid >> 4, jb = (tid & 15) * 4;
            float b0 = 0, b1 = 0, b2 = 0, b3 = 0;
#pragma unroll
            for (int f = 0; f < 16; f++) {
                float pv = p[e * 16 + f];
                const float* vr = &vcur[f * 64 + jb];
                b0 = fmaf(pv, vr[0], b0);
                b1 = fmaf(pv, vr[1], b1);
                b2 = fmaf(pv, vr[2], b2);
                b3 = fmaf(pv, vr[3], b3);
            }
            int base = e * 64 + jb;
            float ds = 0.f;
            if (it == 1) {
                ds = fabsf(b0 - aiprev[base]) + fabsf(b1 - aiprev[base + 1]) +
                     fabsf(b2 - aiprev[base + 2]) + fabsf(b3 - aiprev[base + 3]);
            }
            if (it == 0) {
                aiprev[base] = b0; aiprev[base + 1] = b1;
                aiprev[base + 2] = b2; aiprev[base + 3] = b3;
            }
            if (it >= 1) {
                float* dst = (it == 1) ? g_ai1 : g_ai2;
                size_t g = (size_t)(bb * En + e) * Dn + h * HDn + jb;
                dst[g] = b0; dst[g + 1] = b1; dst[g + 2] = b2; dst[g + 3] = b3;
            }
            qcur[base] += b0; qcur[base + 1] += b1;
            qcur[base + 2] += b2; qcur[base + 3] += b3;
            if (it == 1) {
                float tot = blockReduce256(ds, red);
                if (tid == 0) atomicAdd(&g_diffsum, tot);
            }
        }
        __syncthreads();
    }
}
#define ITER_SMEM ((3 * 64 * WST + 6 * 1024 + 256 + 32) * 4)

// ======================= K4: select ai, Wo proj, atomic into out ==========
#define KSPLIT_OUT 8
__global__ __launch_bounds__(256, 2) void k_out(
    const float* __restrict__ Wo, const float* __restrict__ thrp,
    const float* __restrict__ facp, float* __restrict__ out) {
    extern __shared__ float sh[];
    float diff1 = g_diffsum * (1.0f / 8388608.0f);  // mean over B*H*T*hd
    const float* A = (diff1 < thrp[0] + facp[0] * diff1) ? g_ai1 : g_ai2;
    int j0 = blockIdx.x * 64;
    int kbase = blockIdx.y * (Dn / KSPLIT_OUT);
    u64 acc[4][4] = {};
    gemm_db<Dn / KSPLIT_OUT / 64>(A, Wo, j0, kbase, acc, sh);
    int tid = threadIdx.x;
    int rl = tid & 15, c0 = (tid >> 4) * 4;
#pragma unroll
    for (int i = 0; i < 4; i++) {
        int row = rl + 16 * i;
        int b = row >> 4, t = row & 15;
        size_t base = ((size_t)(b * Tn + t)) * Dn + j0 + c0;
#pragma unroll
        for (int j = 0; j < 4; j++) {
            float2 f = *(float2*)&acc[i][j];
            atomicAdd(&out[base + j], f.x + f.y);
        }
    }
}

// ======================= launch ===========================================
extern "C" void kernel_launch(void* const* d_in, const int* in_sizes, int n_in,
                              void* d_out, int out_size) {
    (void)in_sizes; (void)n_in; (void)out_size;
    const float* x    = (const float*)d_in[0];
    const float* Wq   = (const float*)d_in[1];
    const float* bq   = (const float*)d_in[2];
    const float* Wk   = (const float*)d_in[3];
    const float* Wv   = (const float*)d_in[4];
    const float* bv   = (const float*)d_in[5];
    const float* Wo   = (const float*)d_in[6];
    const float* bo   = (const float*)d_in[7];
    const float* lna  = (const float*)d_in[8];
    const float* lnc  = (const float*)d_in[9];
    const float* lnd  = (const float*)d_in[10];
    const float* Wlq  = (const float*)d_in[11];
    const float* blq  = (const float*)d_in[12];
    const float* Wlk  = (const float*)d_in[13];
    const float* blk  = (const float*)d_in[14];
    const float* Wlv  = (const float*)d_in[15];
    const float* blv  = (const float*)d_in[16];
    const float* temp = (const float*)d_in[17];
    const float* thr  = (const float*)d_in[18];
    const float* fac  = (const float*)d_in[19];
    float* out = (float*)d_out;

    // allow >48KB dynamic smem (host-side attribute set; not a stream op)
    cudaFuncSetAttribute(k_qkv,  cudaFuncAttributeMaxDynamicSharedMemorySize, GEMM_SMEM);
    cudaFuncSetAttribute(k_out,  cudaFuncAttributeMaxDynamicSharedMemorySize, GEMM_SMEM);
    cudaFuncSetAttribute(k_iter, cudaFuncAttributeMaxDynamicSharedMemorySize, ITER_SMEM);

    k_ln_fill<<<1024, 256>>>(x, lna, bq, bv, bo, out);
    k_qkv<<<dim3(16, KSPLIT_QKV, 3), 256, GEMM_SMEM>>>(Wq, Wk, Wv);
    k_iter<<<64, 256, ITER_SMEM>>>(Wlq, blq, Wlk, blk, Wlv, blv, lnc, lnd, temp);
    k_out<<<dim3(16, KSPLIT_OUT, 1), 256, GEMM_SMEM>>>(Wo, thr, fac, out);
}

// round 5
// speedup vs baseline: 2.0082x; 1.0294x over previous
#include <cuda_runtime.h>
#include <math.h>

#define Bn 4
#define Tn 2048
#define Dn 1024
#define Hn 16
#define HDn 64
#define En 16
#define Rn 64                     // Bn*En active rows
#define QK_SCALE 0.35355339059327373f   // hd^-0.25
#define SM_SCALE 0.125f                 // 1/sqrt(hd)

typedef unsigned long long u64;

// ---------------- scratch (static device globals; no allocation) ----------
__device__ float g_xn[Rn * Dn];
__device__ float g_q[Rn * Dn];
__device__ float g_k[Rn * Dn];
__device__ float g_v[Rn * Dn];
__device__ float g_ai1[Rn * Dn];
__device__ float g_ai2[Rn * Dn];
__device__ float g_diffsum;

// ---------------- helpers -------------------------------------------------
__device__ __forceinline__ float warpReduceSum(float v) {
#pragma unroll
    for (int o = 16; o > 0; o >>= 1) v += __shfl_xor_sync(0xffffffffu, v, o);
    return v;
}

__device__ __forceinline__ float blockReduce256(float v, float* sh) {
    __syncthreads();
    v = warpReduceSum(v);
    int wid = threadIdx.x >> 5;
    if ((threadIdx.x & 31) == 0) sh[wid] = v;
    __syncthreads();
    if (threadIdx.x < 32) {
        float t = (threadIdx.x < 8) ? sh[threadIdx.x] : 0.f;
        t = warpReduceSum(t);
        if (threadIdx.x == 0) sh[0] = t;
    }
    __syncthreads();
    return sh[0];
}

// packed fp32x2 FMA (sm_100+): d = a*b + d, lane-wise on a 64-bit pair
__device__ __forceinline__ void ffma2(u64& d, u64 a, u64 b) {
    asm("fma.rn.f32x2 %0, %1, %2, %0;" : "+l"(d) : "l"(a), "l"(b));
}

__device__ __forceinline__ unsigned smem_u32p(const void* p) {
    return (unsigned)__cvta_generic_to_shared(p);
}
__device__ __forceinline__ void cp16(unsigned dst, const void* src) {
    asm volatile("cp.async.cg.shared.global [%0], [%1], 16;" :: "r"(dst), "l"(src));
}
__device__ __forceinline__ void cp8(unsigned dst, const void* src) {
    asm volatile("cp.async.ca.shared.global [%0], [%1], 8;" :: "r"(dst), "l"(src));
}
__device__ __forceinline__ void cp_commit() {
    asm volatile("cp.async.commit_group;");
}
__device__ __forceinline__ void cp_wait0() {
    asm volatile("cp.async.wait_group 0;");
}
// vector float atomic add (sm_90+)
__device__ __forceinline__ void red4(float* p, float a, float b, float c, float d) {
    asm volatile("red.global.add.v4.f32 [%0], {%1,%2,%3,%4};"
                 :: "l"(p), "f"(a), "f"(b), "f"(c), "f"(d) : "memory");
}

// ======================= K1a: LN(64 rows) + accumulator inits =============
__global__ __launch_bounds__(256) void k_ln(
    const float* __restrict__ x, const float* __restrict__ lna,
    const float* __restrict__ bq, const float* __restrict__ bv) {
    if (blockIdx.x < Rn) {
        __shared__ float sh[8];
        if (blockIdx.x == 0 && threadIdx.x == 0) g_diffsum = 0.f;
        int r = blockIdx.x;
        int b = r >> 4, t = r & 15;
        const float* xr = x + ((size_t)(b * Tn + t)) * Dn;
        int tid = threadIdx.x;
        float v[4];
        float s = 0.f;
#pragma unroll
        for (int i = 0; i < 4; i++) { v[i] = xr[tid + i * 256]; s += v[i]; }
        s = blockReduce256(s, sh);
        float mean = s * (1.f / 1024.f);
        float sq = 0.f;
#pragma unroll
        for (int i = 0; i < 4; i++) { float d = v[i] - mean; sq += d * d; }
        sq = blockReduce256(sq, sh);
        float inv = rsqrtf(sq * (1.f / 1024.f) + 1e-5f);
#pragma unroll
        for (int i = 0; i < 4; i++) {
            int j = tid + i * 256;
            g_xn[r * Dn + j] = (v[i] - mean) * inv * lna[j];
        }
    } else {
        // init accumulators with biases (k-split GEMMs red.add onto these)
        int r = blockIdx.x - Rn;
        int tid = threadIdx.x;
#pragma unroll
        for (int i = 0; i < 4; i++) {
            int j = tid + i * 256;
            g_q[r * Dn + j] = bq[j] * QK_SCALE;
            g_k[r * Dn + j] = 0.f;
            g_v[r * Dn + j] = bv[j];
        }
    }
}

// ======================= K1b: bo fill of whole output (side stream) =======
__global__ __launch_bounds__(256) void k_fill(
    const float* __restrict__ bo, float* __restrict__ out) {
    const float4* bo4 = (const float4*)bo;
    float4* o4 = (float4*)out;
    size_t total = (size_t)Bn * Tn * Dn / 4;           // 2,097,152
    size_t start = (size_t)blockIdx.x * 256 + threadIdx.x;
    size_t stride = (size_t)gridDim.x * 256;           // multiple of 256
    float4 v = bo4[start & 255];
    for (size_t i = start; i < total; i += stride) o4[i] = v;
}

// ======================= 64x128 FFMA2 GEMM tile core ======================
// Block computes C[64 x 128] over one K-tile of 64.  128 threads, 8x8 tile.
// A staged with XOR swizzle (conflict-free LDS.64); W staged linear
// (<=2 distinct addrs per phase).  cp.async staging, no prefetch regs.
#define TK 64

__device__ __forceinline__ void stage_tile(
    const float* __restrict__ A, const float* __restrict__ W,
    int j0, int kb, float* sA, float* sW) {
    int tid = threadIdx.x;
    // A: 64 rows x 64 k, 8B chunks, swizzled
#pragma unroll
    for (int c = tid; c < 64 * TK / 2; c += 128) {
        int r = c >> 5;                 // TK/2 = 32 pairs per row
        int kf = (c & 31) * 2;
        int rg = r >> 3;
        int swz = ((rg & 3) * 8) | ((rg >> 2) * 2);
        cp8(smem_u32p(&sA[r * TK + (kf ^ swz)]),
            &A[(size_t)r * Dn + kb + kf]);
    }
    // W: 128 rows x 64 k, 16B chunks, linear
#pragma unroll
    for (int c = tid; c < 128 * TK / 4; c += 128) {
        int r = c >> 4;                 // TK/4 = 16 chunks per row
        int kf = (c & 15) * 4;
        cp16(smem_u32p(&sW[r * TK + kf]),
             &W[(size_t)(j0 + r) * Dn + kb + kf]);
    }
    cp_commit();
}

__device__ __forceinline__ void compute_tile(
    const float* sA, const float* sW, u64* acc, int rg, int cg) {
    int swz = ((rg & 3) * 8) | ((rg >> 2) * 2);
    const float* aBase = sA + rg * 8 * TK;
    const float* wBase = sW + cg * 8 * TK;
#pragma unroll 4
    for (int kk = 0; kk < TK; kk += 2) {
        int ka = kk ^ swz;
        u64 av[8], wv[8];
#pragma unroll
        for (int i = 0; i < 8; i++)
            av[i] = *(const u64*)&aBase[i * TK + ka];
#pragma unroll
        for (int j = 0; j < 8; j++)
            wv[j] = *(const u64*)&wBase[j * TK + kk];
#pragma unroll
        for (int i = 0; i < 8; i++)
#pragma unroll
            for (int j = 0; j < 8; j++) ffma2(acc[i * 8 + j], av[i], wv[j]);
    }
}
#define GEMM_SMEM ((64 + 128) * TK * 4)   // 49152 bytes

// ======================= K2: q,k,v GEMMs (k-split 16, red.v4) =============
__global__ __launch_bounds__(128) void k_qkv(
    const float* __restrict__ Wq, const float* __restrict__ Wk,
    const float* __restrict__ Wv) {
    extern __shared__ float sh[];
    float* sA = sh;
    float* sW = sh + 64 * TK;
    int m = blockIdx.z;
    const float* W = (m == 0) ? Wq : (m == 1) ? Wk : Wv;
    float* dst = (m == 0) ? g_q : (m == 1) ? g_k : g_v;
    float scale = (m == 2) ? 1.0f : QK_SCALE;
    int j0 = blockIdx.x * 128;
    int kb = blockIdx.y * TK;
    u64 acc[64] = {};
    stage_tile(g_xn, W, j0, kb, sA, sW);
    cp_wait0();
    __syncthreads();
    int tid = threadIdx.x, rg = tid & 7, cg = tid >> 3;
    compute_tile(sA, sW, acc, rg, cg);
    int c0 = j0 + cg * 8;
#pragma unroll
    for (int i = 0; i < 8; i++) {
        int row = rg * 8 + i;
        float v[8];
#pragma unroll
        for (int j = 0; j < 8; j++) {
            float2 f = *(float2*)&acc[i * 8 + j];
            v[j] = (f.x + f.y) * scale;
        }
        float* p = &dst[(size_t)row * Dn + c0];
        red4(p, v[0], v[1], v[2], v[3]);
        red4(p + 4, v[4], v[5], v[6], v[7]);
    }
}

// ======================= K3: per-(b,h) 3-iteration attention ==============
#define WST 66                     // small-gemm weight smem row stride
__global__ __launch_bounds__(256) void k_iter(
    const float* __restrict__ Wlq, const float* __restrict__ blq,
    const float* __restrict__ Wlk, const float* __restrict__ blk,
    const float* __restrict__ Wlv, const float* __restrict__ blv,
    const float* __restrict__ lnc, const float* __restrict__ lnd,
    const float* __restrict__ temp_p) {
    extern __shared__ float sm[];
    float* w_all  = sm;                     // 3 * 64*WST
    float* qcur   = w_all + 3 * 64 * WST;
    float* kcur   = qcur + 1024;
    float* vcur   = kcur + 1024;
    float* qlb    = vcur + 1024;
    float* klb    = qlb + 1024;
    float* aiprev = klb + 1024;
    float* p      = aiprev + 1024;          // 256
    float* red    = p + 256;                // 32

    int tid = threadIdx.x;
    int lane = tid & 31;
    int bb = blockIdx.x >> 4;
    int h = blockIdx.x & 15;

    for (int idx = tid; idx < 3 * 4096; idx += 256) {
        int m = idx >> 12, r = idx & 4095, j = r >> 6, d = r & 63;
        const float* Wm = (m == 0) ? Wlq : (m == 1) ? Wlk : Wlv;
        w_all[m * 64 * WST + j * WST + d] = Wm[r];
    }
    for (int i = tid; i < 1024; i += 256) {
        int e = i >> 6, d = i & 63;
        size_t g = (size_t)(bb * En + e) * Dn + h * HDn + d;
        qcur[i] = g_q[g];
        kcur[i] = g_k[g];
        vcur[i] = g_v[g];
    }
    float temp0 = temp_p[0];
    __syncthreads();

    int m = tid / 64;
    int u = tid & 63;
    int e_l = u & 3;
    int j0 = (u >> 2) * 4;

    for (int it = 0; it < 3; it++) {
        u64 acc[4][4] = {};
        if (tid < 192) {
            const float* in = (m == 0) ? qcur : (m == 1) ? kcur : vcur;
            const float* wm = w_all + m * 64 * WST;
#pragma unroll 4
            for (int dd = 0; dd < 32; dd++) {
                int d = (2 * (dd + lane)) & 62;
                u64 iv[4], wv[4];
#pragma unroll
                for (int i = 0; i < 4; i++)
                    iv[i] = *(const u64*)&in[(e_l + 4 * i) * 64 + d];
#pragma unroll
                for (int j = 0; j < 4; j++)
                    wv[j] = *(const u64*)&wm[(j0 + j) * WST + d];
#pragma unroll
                for (int i = 0; i < 4; i++)
#pragma unroll
                    for (int j = 0; j < 4; j++) ffma2(acc[i][j], iv[i], wv[j]);
            }
        }
        __syncthreads();
        if (tid < 192) {
            const float* bl = (m == 0) ? blq : (m == 1) ? blk : blv;
#pragma unroll
            for (int i = 0; i < 4; i++) {
                int e = e_l + 4 * i;
#pragma unroll
                for (int j = 0; j < 4; j++) {
                    float2 f = *(float2*)&acc[i][j];
                    float val = f.x + f.y + bl[j0 + j];
                    int o = e * 64 + j0 + j;
                    if (m == 0) qlb[o] = val;
                    else if (m == 1) { klb[o] = val; kcur[o] = val; }
                    else vcur[o] = val;
                }
            }
        }
        __syncthreads();

        float t_it = temp0 + 0.005f * (float)it;
        float tsc = ((t_it != 1.0f) && (t_it > 0.f)) ? rsqrtf(t_it) : 1.0f;
        int wid = tid >> 5;
        for (int rr = wid; rr < 32; rr += 8) {
            float* buf = (rr < 16) ? (qlb + rr * 64) : (klb + (rr - 16) * 64);
            const float* lw = (rr < 16) ? lnc : lnd;
            float s = (rr < 16) ? tsc * SM_SCALE : 1.0f;
            float v0 = buf[lane], v1 = buf[lane + 32];
            float sum = warpReduceSum(v0 + v1);
            float mean = sum * (1.f / 64.f);
            float d0 = v0 - mean, d1 = v1 - mean;
            float sq = warpReduceSum(d0 * d0 + d1 * d1);
            float inv = rsqrtf(sq * (1.f / 64.f) + 1e-5f);
            buf[lane] = d0 * inv * lw[lane] * s;
            buf[lane + 32] = d1 * inv * lw[lane + 32] * s;
        }
        __syncthreads();

        {
            int e = tid >> 4, f = tid & 15;
            u64 a2 = 0;
#pragma unroll 4
            for (int dd = 0; dd < 32; dd++) {
                int d = (2 * (dd + lane)) & 62;
                ffma2(a2, *(const u64*)&qlb[e * 64 + d],
                          *(const u64*)&klb[f * 64 + d]);
            }
            float2 f2 = *(float2*)&a2;
            p[tid] = f2.x + f2.y;
        }
        __syncthreads();
        if (tid < 16) {
            float mx = -1e30f;
#pragma unroll
            for (int f = 0; f < 16; f++) mx = fmaxf(mx, p[tid * 16 + f]);
            float s = 0.f;
#pragma unroll
            for (int f = 0; f < 16; f++) {
                float ex = expf(p[tid * 16 + f] - mx);
                p[tid * 16 + f] = ex; s += ex;
            }
            float inv = 1.f / s;
#pragma unroll
            for (int f = 0; f < 16; f++) p[tid * 16 + f] *= inv;
        }
        __syncthreads();

        {
            int e = tid >> 4, jb = (tid & 15) * 4;
            float b0 = 0, b1 = 0, b2 = 0, b3 = 0;
#pragma unroll
            for (int f = 0; f < 16; f++) {
                float pv = p[e * 16 + f];
                const float* vr = &vcur[f * 64 + jb];
                b0 = fmaf(pv, vr[0], b0);
                b1 = fmaf(pv, vr[1], b1);
                b2 = fmaf(pv, vr[2], b2);
                b3 = fmaf(pv, vr[3], b3);
            }
            int base = e * 64 + jb;
            float ds = 0.f;
            if (it == 1) {
                ds = fabsf(b0 - aiprev[base]) + fabsf(b1 - aiprev[base + 1]) +
                     fabsf(b2 - aiprev[base + 2]) + fabsf(b3 - aiprev[base + 3]);
            }
            if (it == 0) {
                aiprev[base] = b0; aiprev[base + 1] = b1;
                aiprev[base + 2] = b2; aiprev[base + 3] = b3;
            }
            if (it >= 1) {
                float* dst = (it == 1) ? g_ai1 : g_ai2;
                size_t g = (size_t)(bb * En + e) * Dn + h * HDn + jb;
                dst[g] = b0; dst[g + 1] = b1; dst[g + 2] = b2; dst[g + 3] = b3;
            }
            qcur[base] += b0; qcur[base + 1] += b1;
            qcur[base + 2] += b2; qcur[base + 3] += b3;
            if (it == 1) {
                float tot = blockReduce256(ds, red);
                if (tid == 0) atomicAdd(&g_diffsum, tot);
            }
        }
        __syncthreads();
    }
}
#define ITER_SMEM ((3 * 64 * WST + 6 * 1024 + 256 + 32) * 4)

// ======================= K4: select ai, Wo proj, red.v4 into out ==========
__global__ __launch_bounds__(128) void k_out(
    const float* __restrict__ Wo, const float* __restrict__ thrp,
    const float* __restrict__ facp, float* __restrict__ out) {
    extern __shared__ float sh[];
    float* sA = sh;
    float* sW = sh + 64 * TK;
    float diff1 = g_diffsum * (1.0f / 8388608.0f);  // mean over B*H*T*hd
    const float* A = (diff1 < thrp[0] + facp[0] * diff1) ? g_ai1 : g_ai2;
    int j0 = blockIdx.x * 128;
    int kb = blockIdx.y * TK;
    u64 acc[64] = {};
    stage_tile(A, Wo, j0, kb, sA, sW);
    cp_wait0();
    __syncthreads();
    int tid = threadIdx.x, rg = tid & 7, cg = tid >> 3;
    compute_tile(sA, sW, acc, rg, cg);
    int c0 = j0 + cg * 8;
#pragma unroll
    for (int i = 0; i < 8; i++) {
        int row = rg * 8 + i;
        int b = row >> 4, t = row & 15;
        float v[8];
#pragma unroll
        for (int j = 0; j < 8; j++) {
            float2 f = *(float2*)&acc[i * 8 + j];
            v[j] = f.x + f.y;
        }
        float* p = &out[((size_t)(b * Tn + t)) * Dn + c0];
        red4(p, v[0], v[1], v[2], v[3]);
        red4(p + 4, v[4], v[5], v[6], v[7]);
    }
}

// ======================= launch ===========================================
extern "C" void kernel_launch(void* const* d_in, const int* in_sizes, int n_in,
                              void* d_out, int out_size) {
    (void)in_sizes; (void)n_in; (void)out_size;
    const float* x    = (const float*)d_in[0];
    const float* Wq   = (const float*)d_in[1];
    const float* bq   = (const float*)d_in[2];
    const float* Wk   = (const float*)d_in[3];
    const float* Wv   = (const float*)d_in[4];
    const float* bv   = (const float*)d_in[5];
    const float* Wo   = (const float*)d_in[6];
    const float* bo   = (const float*)d_in[7];
    const float* lna  = (const float*)d_in[8];
    const float* lnc  = (const float*)d_in[9];
    const float* lnd  = (const float*)d_in[10];
    const float* Wlq  = (const float*)d_in[11];
    const float* blq  = (const float*)d_in[12];
    const float* Wlk  = (const float*)d_in[13];
    const float* blk  = (const float*)d_in[14];
    const float* Wlv  = (const float*)d_in[15];
    const float* blv  = (const float*)d_in[16];
    const float* temp = (const float*)d_in[17];
    const float* thr  = (const float*)d_in[18];
    const float* fac  = (const float*)d_in[19];
    float* out = (float*)d_out;

    static cudaStream_t s2 = nullptr;
    static cudaEvent_t evF = nullptr, evJ = nullptr;
    static bool attrs_set = false;
    if (s2 == nullptr) {
        cudaStreamCreateWithFlags(&s2, cudaStreamNonBlocking);
        cudaEventCreateWithFlags(&evF, cudaEventDisableTiming);
        cudaEventCreateWithFlags(&evJ, cudaEventDisableTiming);
    }
    if (!attrs_set) {
        cudaFuncSetAttribute(k_qkv,  cudaFuncAttributeMaxDynamicSharedMemorySize, GEMM_SMEM);
        cudaFuncSetAttribute(k_out,  cudaFuncAttributeMaxDynamicSharedMemorySize, GEMM_SMEM);
        cudaFuncSetAttribute(k_iter, cudaFuncAttributeMaxDynamicSharedMemorySize, ITER_SMEM);
        attrs_set = true;
    }

    // fork: bo-fill runs concurrently on s2
    cudaEventRecord(evF, 0);
    cudaStreamWaitEvent(s2, evF, 0);
    k_fill<<<1024, 256, 0, s2>>>(bo, out);

    // main chain on stream 0
    k_ln<<<128, 256>>>(x, lna, bq, bv);
    k_qkv<<<dim3(8, 16, 3), 128, GEMM_SMEM>>>(Wq, Wk, Wv);
    k_iter<<<64, 256, ITER_SMEM>>>(Wlq, blq, Wlk, blk, Wlv, blv, lnc, lnd, temp);

    // join fill before final projection (which red.adds into out)
    cudaEventRecord(evJ, s2);
    cudaStreamWaitEvent(0, evJ, 0);
    k_out<<<dim3(8, 16), 128, GEMM_SMEM>>>(Wo, thr, fac, out);
}